// round 7
// baseline (speedup 1.0000x reference)
#include <cuda_runtime.h>
#include <cuda_bf16.h>

#define D_MODEL   1024
#define MAX_SEGS  256
#define NTHREADS  256
#define NBLOCKS   296        // one wave: 2 CTAs/SM * 148 SMs
#define TILE      8
#define NORM_CTAS 8

__device__ float g_seg_sum[MAX_SEGS];              // zero-init; finalize re-zeroes
__device__ float g_scratch[MAX_SEGS * D_MODEL];    // zero-init; finalize re-zeroes
__device__ unsigned g_ticket;                      // zero-init; finalize resets
__device__ unsigned g_fin;                         // zero-init; finalize resets
__device__ int      g_release;                     // zero-init; finalize resets

// ---------------------------------------------------------------------------
// Single fused kernel:
//   Phase A: CTA-per-token-range streaming pool (8-token tiles).
//   Phase B: last NORM_CTAS CTAs (by finish ticket) normalize + re-zero state.
// ---------------------------------------------------------------------------
__global__ __launch_bounds__(NTHREADS, 2)
void pool_kernel(const float* __restrict__ x,
                 const int*   __restrict__ cu,
                 const float* __restrict__ Wp,
                 const float* __restrict__ bp,
                 float* __restrict__ out,
                 int T, int nseg) {
    __shared__ float s_part[8][TILE];   // [warp][token]
    __shared__ float s_p[TILE];
    __shared__ int   s_cu[MAX_SEGS + 1];
    __shared__ unsigned s_ticket;

    const int tid  = threadIdx.x;
    const int lane = tid & 31;
    const int wid  = tid >> 5;

    if (tid <= nseg) s_cu[tid] = cu[tid];

    const float4 w = *reinterpret_cast<const float4*>(Wp + tid * 4);
    const float  b = bp[0];

    const int per = (T + NBLOCKS - 1) / NBLOCKS;
    const int t0  = blockIdx.x * per;
    const int t1  = min(t0 + per, T);
    __syncthreads();

    if (t0 < t1) {
        int seg = 0;
        while (s_cu[seg + 1] <= t0) seg++;
        int nb = s_cu[seg + 1];

        float4 acc = make_float4(0.f, 0.f, 0.f, 0.f);
        float  sump = 0.0f;
        const float4* xv = reinterpret_cast<const float4*>(x);

#define FLUSH()                                                            \
        do {                                                               \
            float* o = g_scratch + (size_t)seg * D_MODEL + tid * 4;        \
            atomicAdd(o + 0, acc.x);  atomicAdd(o + 1, acc.y);             \
            atomicAdd(o + 2, acc.z);  atomicAdd(o + 3, acc.w);             \
            if (tid == 0) atomicAdd(&g_seg_sum[seg], sump);                \
        } while (0)

        for (int t = t0; t < t1; t += TILE) {
            const int nvalid = min(TILE, t1 - t);

            // ---- load 8 rows (8 independent LDG.128 per thread) ----
            float4 v[TILE];
#pragma unroll
            for (int j = 0; j < TILE; j++) {
                if (j < nvalid) v[j] = xv[(size_t)(t + j) * 256 + tid];
                else            v[j] = make_float4(0.f, 0.f, 0.f, 0.f);
            }

            // ---- 8 partial dots, pipelined warp reduce ----
            float d[TILE];
#pragma unroll
            for (int j = 0; j < TILE; j++)
                d[j] = v[j].x * w.x + v[j].y * w.y + v[j].z * w.z + v[j].w * w.w;
#pragma unroll
            for (int o = 16; o > 0; o >>= 1) {
#pragma unroll
                for (int j = 0; j < TILE; j++)
                    d[j] += __shfl_xor_sync(0xffffffffu, d[j], o);
            }
            if (lane == 0) {
#pragma unroll
                for (int j = 0; j < TILE; j++) s_part[wid][j] = d[j];
            }
            __syncthreads();

            // ---- warp 0 finishes 8 block-sums + exps ----
            if (wid == 0 && lane < TILE) {
                float s = 0.0f;
#pragma unroll
                for (int ww = 0; ww < 8; ww++) s += s_part[ww][lane];
                s_p[lane] = __expf(s + b);   // unshifted exp: |score| <~ 6
            }
            __syncthreads();

            // ---- accumulate, rare segment-boundary flushes ----
#pragma unroll
            for (int j = 0; j < TILE; j++) {
                const int tt = t + j;
                if (j >= nvalid) break;
                if (tt >= nb) {
                    FLUSH();
                    acc = make_float4(0.f, 0.f, 0.f, 0.f);  sump = 0.0f;
                    do { seg++; nb = s_cu[seg + 1]; } while (tt >= nb);
                }
                const float p = s_p[j];
                sump += p;
                acc.x += p * v[j].x;  acc.y += p * v[j].y;
                acc.z += p * v[j].z;  acc.w += p * v[j].w;
            }
        }
        FLUSH();
#undef FLUSH
    }

    // ------------------- Phase B: ticketed finalize -------------------
    __syncthreads();
    if (tid == 0) {
        __threadfence();                         // flushes visible before ticket
        s_ticket = atomicAdd(&g_ticket, 1u);
    }
    __syncthreads();
    const unsigned ticket = s_ticket;
    if (ticket < NBLOCKS - NORM_CTAS) return;    // early finishers exit

    if (ticket == NBLOCKS - 1) {                 // last CTA: everyone flushed
        if (tid == 0) { __threadfence(); atomicExch(&g_release, 1); }
    } else {
        if (tid == 0) { while (atomicAdd(&g_release, 0) == 0) __nanosleep(128); }
    }
    __syncthreads();
    __threadfence();

    // Normalize: this CTA handles segments s ≡ idx (mod NORM_CTAS).
    const int idx = (int)ticket - (NBLOCKS - NORM_CTAS);
    for (int s = idx; s < nseg; s += NORM_CTAS) {
        const float inv = 1.0f / g_seg_sum[s];
        float4* sc = reinterpret_cast<float4*>(g_scratch + (size_t)s * D_MODEL);
        float4  v  = sc[tid];
        reinterpret_cast<float4*>(out + (size_t)s * D_MODEL)[tid] =
            make_float4(v.x * inv, v.y * inv, v.z * inv, v.w * inv);
        sc[tid] = make_float4(0.f, 0.f, 0.f, 0.f);   // re-zero for next replay
    }
    __syncthreads();
    if (tid == 0) {
        for (int s = idx; s < nseg; s += NORM_CTAS) g_seg_sum[s] = 0.0f;
        __threadfence();
        const unsigned f = atomicAdd(&g_fin, 1u);
        if (f == NORM_CTAS - 1) {                // very last: reset for replay
            atomicExch(&g_ticket, 0u);
            atomicExch(&g_fin, 0u);
            atomicExch(&g_release, 0);
        }
    }
}

// ---------------------------------------------------------------------------
extern "C" void kernel_launch(void* const* d_in, const int* in_sizes, int n_in,
                              void* d_out, int out_size) {
    const float* x  = (const float*)d_in[0];
    const int*   cu = (const int*)  d_in[1];
    const float* W  = (const float*)d_in[2];
    const float* b  = (const float*)d_in[3];
    float* out = (float*)d_out;

    const int T    = in_sizes[0] / D_MODEL;
    const int nseg = in_sizes[1] - 1;

    pool_kernel<<<NBLOCKS, NTHREADS>>>(x, cu, W, b, out, T, nseg);
}

// round 8
// speedup vs baseline: 1.1904x; 1.1904x over previous
#include <cuda_runtime.h>
#include <cuda_bf16.h>

#define D_MODEL   1024
#define MAX_SEGS  256
#define NTHREADS  256
#define NBLOCKS   444        // one wave: 3 CTAs/SM * 148 SMs
#define TILE      8
#define NORM_CTAS 8

__device__ float g_seg_sum[MAX_SEGS];              // zero-init; finalize re-zeroes
__device__ float g_scratch[MAX_SEGS * D_MODEL];    // zero-init; finalize re-zeroes
__device__ unsigned g_ticket;                      // zero-init; finalize resets
__device__ unsigned g_fin;                         // zero-init; finalize resets
__device__ int      g_release;                     // zero-init; finalize resets

// ---------------------------------------------------------------------------
// Single fused kernel:
//   Phase A: CTA-per-token-range streaming pool (8-token tiles).
//   Phase B: last NORM_CTAS CTAs (by finish ticket) normalize + re-zero state.
// ---------------------------------------------------------------------------
__global__ __launch_bounds__(NTHREADS, 3)
void pool_kernel(const float* __restrict__ x,
                 const int*   __restrict__ cu,
                 const float* __restrict__ Wp,
                 const float* __restrict__ bp,
                 float* __restrict__ out,
                 int T, int nseg) {
    __shared__ float s_part[8][TILE];   // [warp][token]
    __shared__ float s_p[TILE];
    __shared__ int   s_cu[MAX_SEGS + 1];
    __shared__ unsigned s_ticket;

    const int tid  = threadIdx.x;
    const int lane = tid & 31;
    const int wid  = tid >> 5;

    if (tid <= nseg) s_cu[tid] = cu[tid];

    const float4 w = *reinterpret_cast<const float4*>(Wp + tid * 4);
    const float  b = bp[0];

    const int per = (T + NBLOCKS - 1) / NBLOCKS;
    const int t0  = blockIdx.x * per;
    const int t1  = min(t0 + per, T);
    __syncthreads();

    if (t0 < t1) {
        int seg = 0;
        while (s_cu[seg + 1] <= t0) seg++;
        int nb = s_cu[seg + 1];

        float4 acc = make_float4(0.f, 0.f, 0.f, 0.f);
        float  sump = 0.0f;
        const float4* xv = reinterpret_cast<const float4*>(x);

#define FLUSH()                                                            \
        do {                                                               \
            float* o = g_scratch + (size_t)seg * D_MODEL + tid * 4;        \
            atomicAdd(o + 0, acc.x);  atomicAdd(o + 1, acc.y);             \
            atomicAdd(o + 2, acc.z);  atomicAdd(o + 3, acc.w);             \
            if (tid == 0) atomicAdd(&g_seg_sum[seg], sump);                \
        } while (0)

        for (int t = t0; t < t1; t += TILE) {
            const int nvalid = min(TILE, t1 - t);

            // ---- load 8 rows (8 independent LDG.128 per thread) ----
            float4 v[TILE];
#pragma unroll
            for (int j = 0; j < TILE; j++) {
                if (j < nvalid) v[j] = xv[(size_t)(t + j) * 256 + tid];
                else            v[j] = make_float4(0.f, 0.f, 0.f, 0.f);
            }

            // ---- 8 partial dots, pipelined warp reduce ----
            float d[TILE];
#pragma unroll
            for (int j = 0; j < TILE; j++)
                d[j] = v[j].x * w.x + v[j].y * w.y + v[j].z * w.z + v[j].w * w.w;
#pragma unroll
            for (int o = 16; o > 0; o >>= 1) {
#pragma unroll
                for (int j = 0; j < TILE; j++)
                    d[j] += __shfl_xor_sync(0xffffffffu, d[j], o);
            }
            if (lane == 0) {
#pragma unroll
                for (int j = 0; j < TILE; j++) s_part[wid][j] = d[j];
            }
            __syncthreads();

            // ---- warp 0 finishes 8 block-sums + exps ----
            if (wid == 0 && lane < TILE) {
                float s = 0.0f;
#pragma unroll
                for (int ww = 0; ww < 8; ww++) s += s_part[ww][lane];
                s_p[lane] = __expf(s + b);   // unshifted exp: |score| <~ 6
            }
            __syncthreads();

            // ---- accumulate, rare segment-boundary flushes ----
#pragma unroll
            for (int j = 0; j < TILE; j++) {
                const int tt = t + j;
                if (j >= nvalid) break;
                if (tt >= nb) {
                    FLUSH();
                    acc = make_float4(0.f, 0.f, 0.f, 0.f);  sump = 0.0f;
                    do { seg++; nb = s_cu[seg + 1]; } while (tt >= nb);
                }
                const float p = s_p[j];
                sump += p;
                acc.x += p * v[j].x;  acc.y += p * v[j].y;
                acc.z += p * v[j].z;  acc.w += p * v[j].w;
            }
        }
        FLUSH();
#undef FLUSH
    }

    // ------------------- Phase B: ticketed finalize -------------------
    __syncthreads();
    if (tid == 0) {
        __threadfence();                         // flushes visible before ticket
        s_ticket = atomicAdd(&g_ticket, 1u);
    }
    __syncthreads();
    const unsigned ticket = s_ticket;
    if (ticket < NBLOCKS - NORM_CTAS) return;    // early finishers exit

    if (ticket == NBLOCKS - 1) {                 // last CTA: everyone flushed
        if (tid == 0) { __threadfence(); atomicExch(&g_release, 1); }
    } else {
        if (tid == 0) { while (atomicAdd(&g_release, 0) == 0) __nanosleep(128); }
    }
    __syncthreads();
    __threadfence();

    // Normalize: this CTA handles segments s ≡ idx (mod NORM_CTAS).
    const int idx = (int)ticket - (NBLOCKS - NORM_CTAS);
    for (int s = idx; s < nseg; s += NORM_CTAS) {
        const float inv = 1.0f / g_seg_sum[s];
        float4* sc = reinterpret_cast<float4*>(g_scratch + (size_t)s * D_MODEL);
        float4  v  = sc[tid];
        reinterpret_cast<float4*>(out + (size_t)s * D_MODEL)[tid] =
            make_float4(v.x * inv, v.y * inv, v.z * inv, v.w * inv);
        sc[tid] = make_float4(0.f, 0.f, 0.f, 0.f);   // re-zero for next replay
    }
    __syncthreads();
    if (tid == 0) {
        for (int s = idx; s < nseg; s += NORM_CTAS) g_seg_sum[s] = 0.0f;
        __threadfence();
        const unsigned f = atomicAdd(&g_fin, 1u);
        if (f == NORM_CTAS - 1) {                // very last: reset for replay
            atomicExch(&g_ticket, 0u);
            atomicExch(&g_fin, 0u);
            atomicExch(&g_release, 0);
        }
    }
}

// ---------------------------------------------------------------------------
extern "C" void kernel_launch(void* const* d_in, const int* in_sizes, int n_in,
                              void* d_out, int out_size) {
    const float* x  = (const float*)d_in[0];
    const int*   cu = (const int*)  d_in[1];
    const float* W  = (const float*)d_in[2];
    const float* b  = (const float*)d_in[3];
    float* out = (float*)d_out;

    const int T    = in_sizes[0] / D_MODEL;
    const int nseg = in_sizes[1] - 1;

    pool_kernel<<<NBLOCKS, NTHREADS>>>(x, cu, W, b, out, T, nseg);
}